// round 2
// baseline (speedup 1.0000x reference)
#include <cuda_runtime.h>

#define BB 512
#define TT 200
#define MM 50
#define DKX 64
#define DVX 64
#define HHX 128
#define NSK 1000
#define NITEMS (BB*TT)

typedef unsigned long long u64;

// ---- packed f32x2 helpers (FFMA2 only reachable via PTX) ----
__device__ __forceinline__ u64 pk2(float lo, float hi) {
    u64 r; asm("mov.b64 %0,{%1,%2};" : "=l"(r) : "f"(lo), "f"(hi)); return r;
}
__device__ __forceinline__ u64 pkd(float x) {
    u64 r; asm("mov.b64 %0,{%1,%1};" : "=l"(r) : "f"(x)); return r;
}
__device__ __forceinline__ void up2(u64 v, float& lo, float& hi) {
    asm("mov.b64 {%0,%1},%2;" : "=f"(lo), "=f"(hi) : "l"(v));
}
__device__ __forceinline__ u64 ffma2(u64 a, u64 b, u64 c) {
    u64 d; asm("fma.rn.f32x2 %0,%1,%2,%3;" : "=l"(d) : "l"(a), "l"(b), "l"(c)); return d;
}

// ---- scratch (device globals; no runtime allocation allowed) ----
__device__ float g_w[NITEMS*MM];      // softmax attention weights  (B,T,M)
__device__ float g_e[NITEMS*DVX];     // erase gates (B,T,DV)
__device__ float g_a[NITEMS*DVX];     // add vectors (B,T,DV)
__device__ float g_read[NITEMS*DVX];  // scan reads  (B,T,DV)

// ============================================================================
// Kernel 1: per-item parallel precompute of w (softmax), e (sigmoid), a (tanh)
// One warp handles 4 items; accumulators packed over item-pairs (f32x2).
// q/v staged interleaved [i*4+k] so item-pairs load as aligned float2.
// ============================================================================
__global__ __launch_bounds__(256,3) void k1_precompute(
    const int*   __restrict__ skill_seq,
    const int*   __restrict__ correct_seq,
    const float* __restrict__ skill_embed,
    const float* __restrict__ key_memory,
    const float* __restrict__ interaction_embed,
    const float* __restrict__ erase_W,
    const float* __restrict__ erase_b,
    const float* __restrict__ add_W,
    const float* __restrict__ add_b)
{
    extern __shared__ float smem[];
    float* sKt = smem;                    // [64][52] transposed, padded
    float* seW = sKt + DKX*52;            // [64*64]
    float* saW = seW + DKX*DVX;           // [64*64]
    float* sq  = saW + DKX*DVX;           // [8 warps][256] layout [i*4+k]
    float* sv  = sq  + 8*256;             // [8 warps][256] layout [i*4+k]

    int tid = threadIdx.x;
    for (int idx = tid; idx < MM*DKX; idx += 256) {
        int m = idx / DKX, i = idx % DKX;
        sKt[i*52 + m] = key_memory[m*DKX + i];
    }
    for (int idx = tid; idx < DKX*DVX; idx += 256) {
        seW[idx] = erase_W[idx];
        saW[idx] = add_W[idx];
    }
    __syncthreads();

    int w    = tid >> 5;
    int lane = tid & 31;
    float eb0 = erase_b[lane], eb1 = erase_b[lane+32];
    float ab0 = add_b[lane],   ab1 = add_b[lane+32];
    float* mq = sq + w*256;
    float* mv = sv + w*256;

    const int nwarps  = gridDim.x * 8;
    const int ngroups = NITEMS / 4;
    const bool v1 = (lane + 32) < MM;   // lane < 18 handles m = lane+32

    for (int g = blockIdx.x*8 + w; g < ngroups; g += nwarps) {
        int base = g * 4;
        #pragma unroll
        for (int k = 0; k < 4; k++) {
            int item = base + k;
            int s = skill_seq[item];
            int c = correct_seq[item];
            mq[lane*4 + k]      = skill_embed[s*DKX + lane];
            mq[(lane+32)*4 + k] = skill_embed[s*DKX + lane+32];
            int vi = s + c*NSK;
            mv[lane*4 + k]      = interaction_embed[vi*DVX + lane];
            mv[(lane+32)*4 + k] = interaction_embed[vi*DVX + lane+32];
        }
        __syncwarp();

        // ---- attention logits: packed over item-pairs (0,1) and (2,3) ----
        u64 d0a = 0ull, d0b = 0ull, d1a = 0ull, d1b = 0ull;
        #pragma unroll 8
        for (int i = 0; i < DKX; i++) {
            u64 q01 = *(const u64*)&mq[i*4];
            u64 q23 = *(const u64*)&mq[i*4 + 2];
            u64 k0  = pkd(sKt[i*52 + lane]);
            u64 k1  = pkd(sKt[i*52 + lane + 32]);
            d0a = ffma2(q01, k0, d0a);
            d0b = ffma2(q23, k0, d0b);
            d1a = ffma2(q01, k1, d1a);
            d1b = ffma2(q23, k1, d1b);
        }
        float d0[4], d1[4];
        up2(d0a, d0[0], d0[1]); up2(d0b, d0[2], d0[3]);
        up2(d1a, d1[0], d1[1]); up2(d1b, d1[2], d1[3]);

        #pragma unroll
        for (int k = 0; k < 4; k++) {
            float mx = fmaxf(d0[k], v1 ? d1[k] : -1e30f);
            #pragma unroll
            for (int off = 16; off > 0; off >>= 1)
                mx = fmaxf(mx, __shfl_xor_sync(0xffffffffu, mx, off));
            float x0 = __expf(d0[k] - mx);
            float x1 = v1 ? __expf(d1[k] - mx) : 0.f;
            float s  = x0 + x1;
            #pragma unroll
            for (int off = 16; off > 0; off >>= 1)
                s += __shfl_xor_sync(0xffffffffu, s, off);
            float inv = 1.f / s;
            int item = base + k;
            g_w[item*MM + lane] = x0 * inv;
            if (v1) g_w[item*MM + lane + 32] = x1 * inv;
        }

        // ---- e = sigmoid(v @ eW + eb), a = tanh(v @ aW + ab), packed pairs ----
        u64 E0a = pkd(eb0), E0b = pkd(eb0), E1a = pkd(eb1), E1b = pkd(eb1);
        u64 A0a = pkd(ab0), A0b = pkd(ab0), A1a = pkd(ab1), A1b = pkd(ab1);
        #pragma unroll 4
        for (int i = 0; i < DVX; i++) {
            u64 v01 = *(const u64*)&mv[i*4];
            u64 v23 = *(const u64*)&mv[i*4 + 2];
            u64 w0 = pkd(seW[i*DVX + lane]);
            u64 w1 = pkd(seW[i*DVX + lane+32]);
            u64 u0 = pkd(saW[i*DVX + lane]);
            u64 u1 = pkd(saW[i*DVX + lane+32]);
            E0a = ffma2(v01, w0, E0a);
            E0b = ffma2(v23, w0, E0b);
            E1a = ffma2(v01, w1, E1a);
            E1b = ffma2(v23, w1, E1b);
            A0a = ffma2(v01, u0, A0a);
            A0b = ffma2(v23, u0, A0b);
            A1a = ffma2(v01, u1, A1a);
            A1b = ffma2(v23, u1, A1b);
        }
        float E0[4], E1[4], A0[4], A1[4];
        up2(E0a, E0[0], E0[1]); up2(E0b, E0[2], E0[3]);
        up2(E1a, E1[0], E1[1]); up2(E1b, E1[2], E1[3]);
        up2(A0a, A0[0], A0[1]); up2(A0b, A0[2], A0[3]);
        up2(A1a, A1[0], A1[1]); up2(A1b, A1[2], A1[3]);
        #pragma unroll
        for (int k = 0; k < 4; k++) {
            int item = base + k;
            g_e[item*DVX + lane]    = 1.f/(1.f + __expf(-E0[k]));
            g_e[item*DVX + lane+32] = 1.f/(1.f + __expf(-E1[k]));
            g_a[item*DVX + lane]    = tanhf(A0[k]);
            g_a[item*DVX + lane+32] = tanhf(A1[k]);
        }
        __syncwarp();
    }
}

// ============================================================================
// Kernel 2: sequential memory scan. One block per batch element, 64 threads.
// Thread = DV column; holds all 50 mem rows as 25 packed f32x2 row-pairs.
// 3 FFMA2 per row-pair per step. w double-buffered in smem (LDS.64 broadcast).
// ============================================================================
__global__ __launch_bounds__(64) void k2_scan(const float* __restrict__ value_init)
{
    __shared__ __align__(16) float sw[2][MM];
    int b = blockIdx.x;
    int v = threadIdx.x;          // 0..63 = DV column

    u64 mem[25];
    #pragma unroll
    for (int m = 0; m < 25; m++)
        mem[m] = pk2(value_init[(2*m)*DVX + v], value_init[(2*m+1)*DVX + v]);

    const int base = b * TT;
    // prefetch t = 0
    float wreg = (v < MM) ? g_w[base*MM + v] : 0.f;
    float ev = g_e[base*DVX + v];
    float av = g_a[base*DVX + v];

    for (int t = 0; t < TT; t++) {
        if (v < MM) sw[t & 1][v] = wreg;
        float e = ev, a = av;
        __syncthreads();
        if (t + 1 < TT) {
            int it = base + t + 1;
            if (v < MM) wreg = g_w[it*MM + v];
            ev = g_e[it*DVX + v];
            av = g_a[it*DVX + v];
        }
        u64 nee = pkd(-e);
        u64 aa  = pkd(a);
        const float* swc = sw[t & 1];
        u64 r2 = 0ull;
        #pragma unroll
        for (int m = 0; m < 25; m++) {
            u64 ww = *(const u64*)&swc[2*m];
            r2 = ffma2(ww, mem[m], r2);        // read with OLD mem
            u64 t1 = ffma2(mem[m], nee, aa);   // a - mem*e
            mem[m] = ffma2(ww, t1, mem[m]);    // mem + w*(a - mem*e)
        }
        float rl, rh; up2(r2, rl, rh);
        g_read[(base + t)*DVX + v] = rl + rh;
    }
}

// ============================================================================
// Kernel 3: output MLP. h = relu([q, read] @ W1 + b1); logit = h @ w2 + b2.
// W1 in shared; one warp per 8 items; accumulators packed over item-pairs.
// x staged with stride 10 (even) so item-pair float2 loads stay 8B-aligned.
// ============================================================================
__global__ __launch_bounds__(256,2) void k3_mlp(
    const int*   __restrict__ skill_seq,
    const int*   __restrict__ correct_seq,
    const float* __restrict__ mask,
    const float* __restrict__ skill_embed,
    const float* __restrict__ fc1_W,
    const float* __restrict__ fc1_b,
    const float* __restrict__ fc2_W,
    const float* __restrict__ fc2_b,
    float*       __restrict__ out)
{
    extern __shared__ float smem[];
    float* sW1 = smem;                    // [128*128]
    float* sw2 = sW1 + HHX*HHX;           // [128]
    float* sb1 = sw2 + HHX;               // [128]
    float* sx  = sb1 + HHX;               // [8 warps][128*10]

    int tid = threadIdx.x;
    for (int idx = tid; idx < HHX*HHX; idx += 256) sW1[idx] = fc1_W[idx];
    if (tid < HHX) { sw2[tid] = fc2_W[tid]; sb1[tid] = fc1_b[tid]; }
    __syncthreads();
    float b2 = fc2_b[0];

    int w    = tid >> 5;
    int lane = tid & 31;
    float* myx = sx + w * (HHX * 10);

    const int nwarps  = gridDim.x * 8;
    const int ngroups = NITEMS / 8;

    for (int g = blockIdx.x*8 + w; g < ngroups; g += nwarps) {
        int base = g * 8;
        // stage x = [q(64), read(64)] transposed: myx[j*10 + k]
        #pragma unroll
        for (int k = 0; k < 8; k++) {
            int item = base + k;
            int s = skill_seq[item];
            myx[(lane)    *10 + k] = skill_embed[s*DKX + lane];
            myx[(lane+32) *10 + k] = skill_embed[s*DKX + lane+32];
            myx[(lane+64) *10 + k] = g_read[item*DVX + lane];
            myx[(lane+96) *10 + k] = g_read[item*DVX + lane+32];
        }
        __syncwarp();

        u64 acc[4][4];   // [c = output col lane*4+c][kk = item-pair]
        #pragma unroll
        for (int c = 0; c < 4; c++) {
            u64 bb = pkd(sb1[lane*4 + c]);
            #pragma unroll
            for (int kk = 0; kk < 4; kk++) acc[c][kk] = bb;
        }
        #pragma unroll 4
        for (int j = 0; j < HHX; j++) {
            float4 wv = *(const float4*)&sW1[j*HHX + lane*4];
            u64 xp[4];
            #pragma unroll
            for (int kk = 0; kk < 4; kk++)
                xp[kk] = *(const u64*)&myx[j*10 + 2*kk];
            u64 wx = pkd(wv.x), wy = pkd(wv.y), wz = pkd(wv.z), wq = pkd(wv.w);
            #pragma unroll
            for (int kk = 0; kk < 4; kk++) {
                acc[0][kk] = ffma2(xp[kk], wx, acc[0][kk]);
                acc[1][kk] = ffma2(xp[kk], wy, acc[1][kk]);
                acc[2][kk] = ffma2(xp[kk], wz, acc[2][kk]);
                acc[3][kk] = ffma2(xp[kk], wq, acc[3][kk]);
            }
        }
        // relu + dot with w2, per-item warp reduction
        float hv[4][8];
        #pragma unroll
        for (int c = 0; c < 4; c++) {
            #pragma unroll
            for (int kk = 0; kk < 4; kk++)
                up2(acc[c][kk], hv[c][2*kk], hv[c][2*kk+1]);
        }
        float part[8];
        #pragma unroll
        for (int k = 0; k < 8; k++) {
            float p = 0.f;
            #pragma unroll
            for (int c = 0; c < 4; c++) {
                float h = fmaxf(hv[c][k], 0.f);
                p = fmaf(h, sw2[lane*4 + c], p);
            }
            part[k] = p;
        }
        #pragma unroll
        for (int off = 16; off > 0; off >>= 1) {
            #pragma unroll
            for (int k = 0; k < 8; k++)
                part[k] += __shfl_xor_sync(0xffffffffu, part[k], off);
        }
        if (lane < 8) {
            int item = base + lane;
            float logit = part[lane] + b2;
            float p = 1.f / (1.f + __expf(-logit));
            float mk = mask[item];
            out[item]          = p * mk;
            out[NITEMS + item] = (float)correct_seq[item] * mk;
        }
        __syncwarp();
    }
}

// ============================================================================
extern "C" void kernel_launch(void* const* d_in, const int* in_sizes, int n_in,
                              void* d_out, int out_size) {
    const int*   skill_seq         = (const int*)  d_in[0];
    const int*   correct_seq       = (const int*)  d_in[1];
    const float* mask              = (const float*)d_in[2];
    const float* skill_embed       = (const float*)d_in[3];
    const float* key_memory        = (const float*)d_in[4];
    const float* value_init        = (const float*)d_in[5];
    const float* interaction_embed = (const float*)d_in[6];
    const float* erase_W           = (const float*)d_in[7];
    const float* erase_b           = (const float*)d_in[8];
    const float* add_W             = (const float*)d_in[9];
    const float* add_b             = (const float*)d_in[10];
    const float* fc1_W             = (const float*)d_in[11];
    const float* fc1_b             = (const float*)d_in[12];
    const float* fc2_W             = (const float*)d_in[13];
    const float* fc2_b             = (const float*)d_in[14];
    float* out = (float*)d_out;

    const int k1_smem = (DKX*52 + 2*DKX*DVX + 2*8*256) * sizeof(float);   // ~62.5 KB
    const int k3_smem = (HHX*HHX + 2*HHX + 8*HHX*10)   * sizeof(float);   // ~107 KB
    cudaFuncSetAttribute(k1_precompute, cudaFuncAttributeMaxDynamicSharedMemorySize, k1_smem);
    cudaFuncSetAttribute(k3_mlp,        cudaFuncAttributeMaxDynamicSharedMemorySize, k3_smem);

    k1_precompute<<<444, 256, k1_smem>>>(skill_seq, correct_seq, skill_embed,
                                         key_memory, interaction_embed,
                                         erase_W, erase_b, add_W, add_b);
    k2_scan<<<BB, 64>>>(value_init);
    k3_mlp<<<296, 256, k3_smem>>>(skill_seq, correct_seq, mask, skill_embed,
                                  fc1_W, fc1_b, fc2_W, fc2_b, out);
}

// round 3
// speedup vs baseline: 2.5672x; 2.5672x over previous
#include <cuda_runtime.h>

#define BB 512
#define TT 200
#define MM 50
#define DKX 64
#define DVX 64
#define HHX 128
#define NSK 1000
#define NITEMS (BB*TT)

typedef unsigned long long u64;

// ---- packed f32x2 helpers ----
__device__ __forceinline__ u64 pk2(float lo, float hi) {
    u64 r; asm("mov.b64 %0,{%1,%2};" : "=l"(r) : "f"(lo), "f"(hi)); return r;
}
__device__ __forceinline__ u64 pkd(float x) {
    u64 r; asm("mov.b64 %0,{%1,%1};" : "=l"(r) : "f"(x)); return r;
}
__device__ __forceinline__ void up2(u64 v, float& lo, float& hi) {
    asm("mov.b64 {%0,%1},%2;" : "=f"(lo), "=f"(hi) : "l"(v));
}
__device__ __forceinline__ u64 ffma2(u64 a, u64 b, u64 c) {
    u64 d; asm("fma.rn.f32x2 %0,%1,%2,%3;" : "=l"(d) : "l"(a), "l"(b), "l"(c)); return d;
}

// ---- tables + scratch (device globals; no runtime allocation allowed) ----
__device__ float tw[NSK*MM];        // softmax(q_s . K^T) per skill
__device__ float te[2*NSK*DVX];     // sigmoid gate per interaction id
__device__ float ta[2*NSK*DVX];     // tanh add per interaction id
__device__ float qW[NSK*HHX];       // skill_embed[s] @ W1_top + b1
__device__ float g_read[NITEMS*DVX];

// ============================================================================
// Kernel 0: build all tables. Block role by blockIdx:
//   [0,125)   role A: tw    (8 skills/block, 1 per warp)
//   [125,375) role B: te/ta (8 vis/block, 1 per warp)
//   [375,407) role C: qW    (32 skills/block, 4 per warp)
// ============================================================================
__global__ __launch_bounds__(256) void k0_tables(
    const float* __restrict__ skill_embed,
    const float* __restrict__ key_memory,
    const float* __restrict__ interaction_embed,
    const float* __restrict__ erase_W,
    const float* __restrict__ erase_b,
    const float* __restrict__ add_W,
    const float* __restrict__ add_b,
    const float* __restrict__ fc1_W,
    const float* __restrict__ fc1_b)
{
    extern __shared__ float smem[];
    int tid  = threadIdx.x;
    int w    = tid >> 5;
    int lane = tid & 31;
    int bid  = blockIdx.x;

    if (bid < 125) {
        // ---------------- role A: attention softmax table ----------------
        float* sKt = smem;            // [64][52] transposed
        float* sq  = sKt + DKX*52;    // [8 warps][64]
        for (int idx = tid; idx < MM*DKX; idx += 256) {
            int m = idx / DKX, i = idx % DKX;
            sKt[i*52 + m] = key_memory[m*DKX + i];
        }
        __syncthreads();
        int s = bid*8 + w;            // < 1000 always (125*8)
        float* mq = sq + w*64;
        mq[lane]    = skill_embed[s*DKX + lane];
        mq[lane+32] = skill_embed[s*DKX + lane+32];
        __syncwarp();
        const bool v1 = (lane + 32) < MM;
        float d0 = 0.f, d1 = 0.f;
        #pragma unroll 8
        for (int i = 0; i < DKX; i++) {
            float qi = mq[i];
            d0 = fmaf(qi, sKt[i*52 + lane], d0);
            d1 = fmaf(qi, sKt[i*52 + lane + 32], d1);
        }
        float mx = fmaxf(d0, v1 ? d1 : -1e30f);
        #pragma unroll
        for (int off = 16; off > 0; off >>= 1)
            mx = fmaxf(mx, __shfl_xor_sync(0xffffffffu, mx, off));
        float x0 = __expf(d0 - mx);
        float x1 = v1 ? __expf(d1 - mx) : 0.f;
        float sm = x0 + x1;
        #pragma unroll
        for (int off = 16; off > 0; off >>= 1)
            sm += __shfl_xor_sync(0xffffffffu, sm, off);
        float inv = 1.f / sm;
        tw[s*MM + lane] = x0 * inv;
        if (v1) tw[s*MM + lane + 32] = x1 * inv;
    } else if (bid < 375) {
        // ---------------- role B: gate tables ----------------
        float* seW = smem;            // [64*64]
        float* saW = seW + DKX*DVX;   // [64*64]
        float* sv  = saW + DKX*DVX;   // [8 warps][64]
        for (int idx = tid; idx < DKX*DVX; idx += 256) {
            seW[idx] = erase_W[idx];
            saW[idx] = add_W[idx];
        }
        __syncthreads();
        int vi = (bid - 125)*8 + w;   // < 2000
        float* mv = sv + w*64;
        mv[lane]    = interaction_embed[vi*DVX + lane];
        mv[lane+32] = interaction_embed[vi*DVX + lane+32];
        __syncwarp();
        float E0 = erase_b[lane], E1 = erase_b[lane+32];
        float A0 = add_b[lane],   A1 = add_b[lane+32];
        #pragma unroll 8
        for (int i = 0; i < DVX; i++) {
            float vv = mv[i];
            E0 = fmaf(vv, seW[i*DVX + lane],    E0);
            E1 = fmaf(vv, seW[i*DVX + lane+32], E1);
            A0 = fmaf(vv, saW[i*DVX + lane],    A0);
            A1 = fmaf(vv, saW[i*DVX + lane+32], A1);
        }
        te[vi*DVX + lane]    = 1.f/(1.f + __expf(-E0));
        te[vi*DVX + lane+32] = 1.f/(1.f + __expf(-E1));
        ta[vi*DVX + lane]    = tanhf(A0);
        ta[vi*DVX + lane+32] = tanhf(A1);
    } else {
        // ---------------- role C: qW table ----------------
        float* sW1t = smem;            // [64][128] top rows of fc1_W
        float* sb1  = sW1t + 64*HHX;   // [128]
        float* sq   = sb1 + HHX;       // [8 warps][256] layout [i*4+k]
        for (int idx = tid; idx < 64*HHX; idx += 256) sW1t[idx] = fc1_W[idx];
        if (tid < HHX) sb1[tid] = fc1_b[tid];
        __syncthreads();
        int sbase = (bid - 375)*32 + w*4;
        float* mq = sq + w*256;
        #pragma unroll
        for (int k = 0; k < 4; k++) {
            int s = sbase + k; if (s >= NSK) s = NSK-1;
            mq[lane*4 + k]      = skill_embed[s*DKX + lane];
            mq[(lane+32)*4 + k] = skill_embed[s*DKX + lane+32];
        }
        __syncwarp();
        u64 acc2[4][2];
        #pragma unroll
        for (int c = 0; c < 4; c++) {
            u64 bb = pkd(sb1[lane*4 + c]);
            acc2[c][0] = bb; acc2[c][1] = bb;
        }
        #pragma unroll 4
        for (int i = 0; i < DKX; i++) {
            u64 q01 = *(const u64*)&mq[i*4];
            u64 q23 = *(const u64*)&mq[i*4 + 2];
            float4 w4 = *(const float4*)&sW1t[i*HHX + lane*4];
            u64 wx = pkd(w4.x), wy = pkd(w4.y), wz = pkd(w4.z), wq = pkd(w4.w);
            acc2[0][0] = ffma2(q01, wx, acc2[0][0]);
            acc2[0][1] = ffma2(q23, wx, acc2[0][1]);
            acc2[1][0] = ffma2(q01, wy, acc2[1][0]);
            acc2[1][1] = ffma2(q23, wy, acc2[1][1]);
            acc2[2][0] = ffma2(q01, wz, acc2[2][0]);
            acc2[2][1] = ffma2(q23, wz, acc2[2][1]);
            acc2[3][0] = ffma2(q01, wq, acc2[3][0]);
            acc2[3][1] = ffma2(q23, wq, acc2[3][1]);
        }
        float A[4][4];
        #pragma unroll
        for (int c = 0; c < 4; c++) {
            up2(acc2[c][0], A[c][0], A[c][1]);
            up2(acc2[c][1], A[c][2], A[c][3]);
        }
        #pragma unroll
        for (int k = 0; k < 4; k++) {
            int s = sbase + k;
            if (s < NSK) {
                float4 o = make_float4(A[0][k], A[1][k], A[2][k], A[3][k]);
                *(float4*)&qW[s*HHX + lane*4] = o;
            }
        }
    }
}

// ============================================================================
// Kernel 2: sequential memory scan. One block per batch element, 64 threads.
// Thread = DV column; mem = 25 packed f32x2 row-pairs in registers.
// Indices staged in smem up-front; table rows prefetched one step ahead.
// ============================================================================
__global__ __launch_bounds__(64) void k2_scan(
    const float* __restrict__ value_init,
    const int*   __restrict__ skill_seq,
    const int*   __restrict__ correct_seq)
{
    __shared__ __align__(8) float sw[2][52];
    __shared__ int ss[TT];
    __shared__ int svi[TT];
    int b = blockIdx.x;
    int v = threadIdx.x;          // 0..63 = DV column
    const int base = b * TT;

    for (int i = v; i < TT; i += 64) {
        int s = skill_seq[base + i];
        ss[i]  = s;
        svi[i] = s + correct_seq[base + i]*NSK;
    }
    u64 mem[25];
    #pragma unroll
    for (int m = 0; m < 25; m++)
        mem[m] = pk2(value_init[(2*m)*DVX + v], value_init[(2*m+1)*DVX + v]);
    __syncthreads();

    int s0 = ss[0], vi0 = svi[0];
    float wreg = (v < MM) ? tw[s0*MM + v] : 0.f;
    float ev = te[vi0*DVX + v];
    float av = ta[vi0*DVX + v];

    for (int t = 0; t < TT; t++) {
        if (v < MM) sw[t & 1][v] = wreg;
        float e = ev, a = av;
        __syncthreads();
        if (t + 1 < TT) {
            int s1 = ss[t+1], vi1 = svi[t+1];
            wreg = (v < MM) ? tw[s1*MM + v] : 0.f;
            ev = te[vi1*DVX + v];
            av = ta[vi1*DVX + v];
        }
        u64 nee = pkd(-e);
        u64 aa  = pkd(a);
        const float* swc = sw[t & 1];
        u64 r[4] = {0ull,0ull,0ull,0ull};
        #pragma unroll
        for (int m = 0; m < 25; m++) {
            u64 ww = *(const u64*)&swc[2*m];
            r[m & 3] = ffma2(ww, mem[m], r[m & 3]);   // read with OLD mem
            u64 t1 = ffma2(mem[m], nee, aa);          // a - mem*e
            mem[m] = ffma2(ww, t1, mem[m]);           // mem + w*(a - mem*e)
        }
        float rl0, rh0, rl1, rh1;
        u64 rA = ffma2(r[0], pkd(1.f), r[1]);  // r0+r1 (use add via fma)
        u64 rB = ffma2(r[2], pkd(1.f), r[3]);
        up2(rA, rl0, rh0); up2(rB, rl1, rh1);
        g_read[(base + t)*DVX + v] = (rl0 + rh0) + (rl1 + rh1);
    }
}

// ============================================================================
// Kernel 3: output MLP, read-half only: h = relu(qW[s] + read @ W1_low);
// logit = h @ w2 + b2. W1_low (32KB) in shared; one warp per 8 items.
// ============================================================================
__global__ __launch_bounds__(256,3) void k3_mlp(
    const int*   __restrict__ skill_seq,
    const int*   __restrict__ correct_seq,
    const float* __restrict__ mask,
    const float* __restrict__ fc1_W,
    const float* __restrict__ fc2_W,
    const float* __restrict__ fc2_b,
    float*       __restrict__ out)
{
    extern __shared__ float smem[];
    float* sW1 = smem;                    // [64][128] = fc1_W rows 64..127
    float* sw2 = sW1 + 64*HHX;            // [128]
    float* sx  = sw2 + HHX;               // [8 warps][64*10]

    int tid = threadIdx.x;
    for (int idx = tid; idx < 64*HHX; idx += 256) sW1[idx] = fc1_W[64*HHX + idx];
    if (tid < HHX) sw2[tid] = fc2_W[tid];
    __syncthreads();
    float b2 = fc2_b[0];

    int w    = tid >> 5;
    int lane = tid & 31;
    float* myx = sx + w * (64 * 10);

    const int nwarps  = gridDim.x * 8;
    const int ngroups = NITEMS / 8;

    for (int g = blockIdx.x*8 + w; g < ngroups; g += nwarps) {
        int base = g * 8;
        float4 qk[8];
        int items_s[8];
        #pragma unroll
        for (int k = 0; k < 8; k++) {
            int item = base + k;
            int s = skill_seq[item];
            items_s[k] = s;
            qk[k] = *(const float4*)&qW[s*HHX + lane*4];
            myx[(lane)    *10 + k] = g_read[item*DVX + lane];
            myx[(lane+32) *10 + k] = g_read[item*DVX + lane+32];
        }
        __syncwarp();

        u64 acc[4][4];   // [c][item-pair]
        #pragma unroll
        for (int kk = 0; kk < 4; kk++) {
            acc[0][kk] = pk2(qk[2*kk].x, qk[2*kk+1].x);
            acc[1][kk] = pk2(qk[2*kk].y, qk[2*kk+1].y);
            acc[2][kk] = pk2(qk[2*kk].z, qk[2*kk+1].z);
            acc[3][kk] = pk2(qk[2*kk].w, qk[2*kk+1].w);
        }
        #pragma unroll 4
        for (int j = 0; j < 64; j++) {
            float4 wv = *(const float4*)&sW1[j*HHX + lane*4];
            u64 xp[4];
            #pragma unroll
            for (int kk = 0; kk < 4; kk++)
                xp[kk] = *(const u64*)&myx[j*10 + 2*kk];
            u64 wx = pkd(wv.x), wy = pkd(wv.y), wz = pkd(wv.z), wq = pkd(wv.w);
            #pragma unroll
            for (int kk = 0; kk < 4; kk++) {
                acc[0][kk] = ffma2(xp[kk], wx, acc[0][kk]);
                acc[1][kk] = ffma2(xp[kk], wy, acc[1][kk]);
                acc[2][kk] = ffma2(xp[kk], wz, acc[2][kk]);
                acc[3][kk] = ffma2(xp[kk], wq, acc[3][kk]);
            }
        }
        // relu + dot with w2, per-item warp reduction
        float hv[4][8];
        #pragma unroll
        for (int c = 0; c < 4; c++) {
            #pragma unroll
            for (int kk = 0; kk < 4; kk++)
                up2(acc[c][kk], hv[c][2*kk], hv[c][2*kk+1]);
        }
        float part[8];
        #pragma unroll
        for (int k = 0; k < 8; k++) {
            float p = 0.f;
            #pragma unroll
            for (int c = 0; c < 4; c++) {
                float h = fmaxf(hv[c][k], 0.f);
                p = fmaf(h, sw2[lane*4 + c], p);
            }
            part[k] = p;
        }
        #pragma unroll
        for (int off = 16; off > 0; off >>= 1) {
            #pragma unroll
            for (int k = 0; k < 8; k++)
                part[k] += __shfl_xor_sync(0xffffffffu, part[k], off);
        }
        if (lane < 8) {
            int item = base + lane;
            float logit = part[lane] + b2;
            float p = 1.f / (1.f + __expf(-logit));
            float mk = mask[item];
            out[item]          = p * mk;
            out[NITEMS + item] = (float)correct_seq[item] * mk;
        }
        __syncwarp();
    }
}

// ============================================================================
extern "C" void kernel_launch(void* const* d_in, const int* in_sizes, int n_in,
                              void* d_out, int out_size) {
    const int*   skill_seq         = (const int*)  d_in[0];
    const int*   correct_seq       = (const int*)  d_in[1];
    const float* mask              = (const float*)d_in[2];
    const float* skill_embed       = (const float*)d_in[3];
    const float* key_memory        = (const float*)d_in[4];
    const float* value_init        = (const float*)d_in[5];
    const float* interaction_embed = (const float*)d_in[6];
    const float* erase_W           = (const float*)d_in[7];
    const float* erase_b           = (const float*)d_in[8];
    const float* add_W             = (const float*)d_in[9];
    const float* add_b             = (const float*)d_in[10];
    const float* fc1_W             = (const float*)d_in[11];
    const float* fc1_b             = (const float*)d_in[12];
    const float* fc2_W             = (const float*)d_in[13];
    const float* fc2_b             = (const float*)d_in[14];
    float* out = (float*)d_out;

    // k0 smem = max(roleA, roleB, roleC) floats
    const int k0_smem = (64*HHX + HHX + 8*256) * sizeof(float);           // ~41.5 KB
    const int k3_smem = (64*HHX + HHX + 8*64*10) * sizeof(float);         // ~53 KB
    cudaFuncSetAttribute(k3_mlp, cudaFuncAttributeMaxDynamicSharedMemorySize, k3_smem);

    k0_tables<<<407, 256, k0_smem>>>(skill_embed, key_memory, interaction_embed,
                                     erase_W, erase_b, add_W, add_b, fc1_W, fc1_b);
    k2_scan<<<BB, 64>>>(value_init, skill_seq, correct_seq);
    k3_mlp<<<296, 256, k3_smem>>>(skill_seq, correct_seq, mask,
                                  fc1_W, fc2_W, fc2_b, out);
}